// round 16
// baseline (speedup 1.0000x reference)
#include <cuda_runtime.h>
#include <cstdint>
#include <math.h>

// Problem constants
#define NBINS (1 << 21)          // 128^3
#define NPIX  (4096 * 4096)      // 16,777,216 pixels
#define NGRP  (NPIX / 4)         // 4-pixel groups
#define NFLAGW (NBINS / 32)      // 65536 flag words
#define NCHUNK (NBINS / 32)      // 65536 32-bin chunks
#define FGRID  148               // fused kernel: one block per SM (co-resident)
#define FWARPS (FGRID * 32)      // 4736 warps
#define CPT    14                // ceil(65536 / 4736) chunks per warp
#define RED_BLOCKS 2048          // k_hist blocks that also reduce full/lines

// Fixed-point mask accumulation: 24 fractional bits, count in bits [40:64)
#define MASK_SCALE 16777216.0f        // 2^24
#define MASK_INV_SCALE (1.0f / 16777216.0f)
#define MASK_INV_SCALE_D (1.0 / 16777216.0)
#define COUNT_SHIFT 40
#define MASK40 0xFFFFFFFFFFULL        // low 40 bits
#define BIN21 0x1FFFFF

// k_out smem bit-table: 57344 words = 224 KB, 1 block/SM (proven config)
#define SMEM_WORDS 57344
#define SMEM_BYTES (SMEM_WORDS * 4)

// Scratch (allocation-free rule: __device__ globals; zero-initialized at load)
__device__ unsigned long long g_hist[NBINS];   // 16 MB, packed count|mask
__device__ unsigned long long g_b64[NGRP];     // 32 MB: bins 0..2 of each group (21b each)
__device__ unsigned int       g_b32[NGRP];     // 16 MB: bin 3 of each group
__device__ unsigned int       g_flag[NFLAGW];  // 256 KB bit table
__device__ double             g_sumf_in, g_suml_in, g_avg;
__device__ unsigned long long g_mask_total;
__device__ unsigned int       g_bar1;          // software grid barrier
// Scalars/barrier are reset by k_out (which doesn't read them) for the NEXT
// call; load-time zero-init covers the first call.

// ---------------------------------------------------------------------------
// K1: histogram accumulate + packed bin store (4 px/thread, proven shape).
// Also hoists ALL the global reductions that used to be k_fused Phase A:
//  - g_mask_total: sum of the SAME quantized u64 pixel masks (integer —
//    exactly equal to the old bin-side sum).
//  - g_sumf_in / g_suml_in: first RED_BLOCKS blocks reduce full_in/lines_in
//    (float partials -> double atomics, same structure as the proven k_sums).
// ---------------------------------------------------------------------------
__global__ void __launch_bounds__(256) k_hist(const int* __restrict__ img,
                                              const float* __restrict__ mask,
                                              const float* __restrict__ full_in,
                                              const float* __restrict__ lines_in) {
    int t = blockIdx.x * blockDim.x + threadIdx.x;   // 0 .. NPIX/4-1
    if (t >= NPIX / 4) return;

    const int4* img4 = (const int4*)img;
    int4 a = __ldcs(&img4[t * 3 + 0]);
    int4 b = __ldcs(&img4[t * 3 + 1]);
    int4 c = __ldcs(&img4[t * 3 + 2]);
    float4 m = __ldcs(&((const float4*)mask)[t]);

    int bin0 = ((a.x >> 1) << 14) | ((a.y >> 1) << 7) | (a.z >> 1);
    int bin1 = ((a.w >> 1) << 14) | ((b.x >> 1) << 7) | (b.y >> 1);
    int bin2 = ((b.z >> 1) << 14) | ((b.w >> 1) << 7) | (c.x >> 1);
    int bin3 = ((c.y >> 1) << 14) | ((c.z >> 1) << 7) | (c.w >> 1);

    unsigned long long q0 = (unsigned long long)(m.x * MASK_SCALE + 0.5f);
    unsigned long long q1 = (unsigned long long)(m.y * MASK_SCALE + 0.5f);
    unsigned long long q2 = (unsigned long long)(m.z * MASK_SCALE + 0.5f);
    unsigned long long q3 = (unsigned long long)(m.w * MASK_SCALE + 0.5f);

    atomicAdd(&g_hist[bin0], (1ULL << COUNT_SHIFT) | q0);
    atomicAdd(&g_hist[bin1], (1ULL << COUNT_SHIFT) | q1);
    atomicAdd(&g_hist[bin2], (1ULL << COUNT_SHIFT) | q2);
    atomicAdd(&g_hist[bin3], (1ULL << COUNT_SHIFT) | q3);

    unsigned long long w = (unsigned long long)(unsigned int)bin0
                         | ((unsigned long long)(unsigned int)bin1 << 21)
                         | ((unsigned long long)(unsigned int)bin2 << 42);
    __stcs(&g_b64[t], w);
    __stcs(&g_b32[t], (unsigned int)bin3);

    // ---- hoisted reductions ----
    unsigned long long msum = q0 + q1 + q2 + q3;
    float fsum = 0.0f, lsum = 0.0f;
    bool red = (blockIdx.x < RED_BLOCKS);          // t < NBINS/4 exactly
    if (red) {
        float4 f4 = __ldcs(&((const float4*)full_in)[t]);
        float4 l4 = __ldcs(&((const float4*)lines_in)[t]);
        fsum = (f4.x + f4.y) + (f4.z + f4.w);
        lsum = (l4.x + l4.y) + (l4.z + l4.w);
    }
    for (int o = 16; o > 0; o >>= 1) {
        msum += __shfl_down_sync(0xFFFFFFFFu, msum, o);
        fsum += __shfl_down_sync(0xFFFFFFFFu, fsum, o);
        lsum += __shfl_down_sync(0xFFFFFFFFu, lsum, o);
    }
    __shared__ unsigned long long sm[8];
    __shared__ float sf[8], sl[8];
    int lane = threadIdx.x & 31, wid = threadIdx.x >> 5;
    if (lane == 0) { sm[wid] = msum; sf[wid] = fsum; sl[wid] = lsum; }
    __syncthreads();
    if (wid == 0) {
        msum = (lane < 8) ? sm[lane] : 0ULL;
        fsum = (lane < 8) ? sf[lane] : 0.0f;
        lsum = (lane < 8) ? sl[lane] : 0.0f;
        for (int o = 4; o > 0; o >>= 1) {
            msum += __shfl_down_sync(0xFFFFFFFFu, msum, o);
            fsum += __shfl_down_sync(0xFFFFFFFFu, fsum, o);
            lsum += __shfl_down_sync(0xFFFFFFFFu, lsum, o);
        }
        if (lane == 0) {
            atomicAdd(&g_mask_total, msum);
            if (red) {
                atomicAdd(&g_sumf_in, (double)fsum);
                atomicAdd(&g_suml_in, (double)lsum);
            }
        }
    }
}

// ---------------------------------------------------------------------------
// K2 (fused): log-ratio + avg + flag table. Phase A is gone — all totals were
// computed by k_hist and are visible at the kernel boundary. ONE grid barrier.
// Phase B zeroes each hist bin after its final read (sole owner per the chunk
// partition), leaving g_hist clean for the next graph replay.
// ---------------------------------------------------------------------------
__device__ __forceinline__ void grid_barrier(unsigned int* bar) {
    __syncthreads();
    if (threadIdx.x == 0) {
        __threadfence();
        atomicAdd(bar, 1u);
        while (*((volatile unsigned int*)bar) < FGRID) { }
        __threadfence();
    }
    __syncthreads();
}

__global__ void __launch_bounds__(1024) k_fused(const float* __restrict__ full_in,
                                                const float* __restrict__ lines_in) {
    int tid  = threadIdx.x;
    int lane = tid & 31;
    int wid  = tid >> 5;
    int W    = blockIdx.x * 32 + wid;    // global warp id, 0..4735

    // Derive scalars (identical doubles in every block; inputs written by k_hist)
    __shared__ float sC, sInvSl;
    if (tid == 0) {
        double sfd = g_sumf_in + (double)NPIX + (double)NBINS;
        double sld = g_suml_in + (double)g_mask_total * MASK_INV_SCALE_D
                   + (double)NBINS * 1e-10;
        sC = (float)(log(sfd) - log(sld));
        sInvSl = (float)(1.0 / sld);
    }
    __syncthreads();
    float C = sC, inv_sl = sInvSl;

    // ---------------- Phase B: log ratios (register-resident) + avg ----------
    float lr[CPT];
    float avg = 0.0f;
    #pragma unroll
    for (int j = 0; j < CPT; j++) {
        int c = W + j * FWARPS;
        if (c < NCHUNK) {                 // warp-uniform guard
            int bin = c * 32 + lane;
            unsigned long long h = g_hist[bin];
            g_hist[bin] = 0ULL;           // zero for next call (sole owner)
            float cnt = (float)(h >> COUNT_SHIFT);
            float ms  = (float)(h & MASK40) * MASK_INV_SCALE;
            float f = full_in[bin] + cnt + 1.0f;
            float l = lines_in[bin] + ms + 1e-10f;
            float v = __logf(l) - __logf(f) + C;   // no divide (proven bit-identical)
            lr[j] = v;
            avg += (l * inv_sl) * v;
        } else {
            lr[j] = 0.0f;
        }
    }
    for (int o = 16; o > 0; o >>= 1)
        avg += __shfl_down_sync(0xFFFFFFFFu, avg, o);
    __shared__ float sa[32];
    if (lane == 0) sa[wid] = avg;
    __syncthreads();
    if (wid == 0) {
        avg = sa[lane];
        for (int o = 16; o > 0; o >>= 1)
            avg += __shfl_down_sync(0xFFFFFFFFu, avg, o);
        if (lane == 0) atomicAdd(&g_avg, (double)avg);
    }
    grid_barrier(&g_bar1);

    // ---------------- Phase C: flag bits via ballot ----------------
    float avgf = (float)(*((volatile double*)&g_avg));
    #pragma unroll
    for (int j = 0; j < CPT; j++) {
        int c = W + j * FWARPS;
        if (c < NCHUNK) {                 // warp-uniform: full-warp ballot
            unsigned int m = __ballot_sync(0xFFFFFFFFu, lr[j] > avgf);
            if (lane == 0) g_flag[c] = m;
        }
    }
}

// ---------------------------------------------------------------------------
// K4: gather from packed bins (12B/4px). 224KB bit table in smem, rest via
// L2-resident g_flag. Streams evict-first. 148 blocks x 1024 threads.
// Block 0 thread 0 also resets the scalar accumulators + barrier counter for
// the next graph replay (k_out never reads them — race-free).
// ---------------------------------------------------------------------------
__global__ void __launch_bounds__(1024) k_out(float* __restrict__ out) {
    if (blockIdx.x == 0 && threadIdx.x == 0) {
        g_sumf_in = 0.0; g_suml_in = 0.0; g_avg = 0.0;
        g_mask_total = 0ULL;
        g_bar1 = 0u;
    }
    extern __shared__ unsigned int s_flag[];
    for (int i = threadIdx.x; i < SMEM_WORDS; i += 1024)
        s_flag[i] = g_flag[i];
    __syncthreads();

    int stride = gridDim.x * 1024;
    for (int t = blockIdx.x * 1024 + threadIdx.x; t < NPIX / 4; t += stride) {
        unsigned long long ww = __ldcs(&g_b64[t]);
        unsigned int       xx = __ldcs(&g_b32[t]);
        int b0 = (int)( ww        & BIN21);
        int b1 = (int)((ww >> 21) & BIN21);
        int b2 = (int)( ww >> 42);
        int b3 = (int)xx;
        float4 o;
        {
            int w = b0 >> 5, bit = b0 & 31;
            unsigned int word = (w < SMEM_WORDS) ? s_flag[w] : __ldg(&g_flag[w]);
            o.x = (float)((word >> bit) & 1u);
        }
        {
            int w = b1 >> 5, bit = b1 & 31;
            unsigned int word = (w < SMEM_WORDS) ? s_flag[w] : __ldg(&g_flag[w]);
            o.y = (float)((word >> bit) & 1u);
        }
        {
            int w = b2 >> 5, bit = b2 & 31;
            unsigned int word = (w < SMEM_WORDS) ? s_flag[w] : __ldg(&g_flag[w]);
            o.z = (float)((word >> bit) & 1u);
        }
        {
            int w = b3 >> 5, bit = b3 & 31;
            unsigned int word = (w < SMEM_WORDS) ? s_flag[w] : __ldg(&g_flag[w]);
            o.w = (float)((word >> bit) & 1u);
        }
        __stcs(&((float4*)out)[t], o);
    }
}

extern "C" void kernel_launch(void* const* d_in, const int* in_sizes, int n_in,
                              void* d_out, int out_size) {
    const int*   img      = (const int*)d_in[0];
    const float* mask     = (const float*)d_in[1];
    const float* full_in  = (const float*)d_in[2];
    const float* lines_in = (const float*)d_in[3];
    float* out            = (float*)d_out;

    // Idempotent opt-in for 224KB dynamic smem (non-stream call; capture-safe).
    cudaFuncSetAttribute(k_out, cudaFuncAttributeMaxDynamicSharedMemorySize, SMEM_BYTES);

    k_hist <<<(NPIX / 4) / 256, 256>>>(img, mask, full_in, lines_in);
    k_fused<<<FGRID, 1024>>>(full_in, lines_in);
    k_out  <<<148, 1024, SMEM_BYTES>>>(out);
}

// round 17
// speedup vs baseline: 1.1695x; 1.1695x over previous
#include <cuda_runtime.h>
#include <cstdint>
#include <math.h>

// Problem constants
#define NBINS (1 << 21)          // 128^3
#define NPIX  (4096 * 4096)      // 16,777,216 pixels
#define NGRP  (NPIX / 4)         // 4-pixel groups
#define NFLAGW (NBINS / 32)      // 65536 flag words
#define NCHUNK (NBINS / 32)      // 65536 32-bin chunks
#define FGRID  148               // fused kernel: one block per SM (co-resident)
#define FWARPS (FGRID * 32)      // 4736 warps
#define CPT    14                // ceil(65536 / 4736) chunks per warp

// Fixed-point mask accumulation: 24 fractional bits, count in bits [40:64)
#define MASK_SCALE 16777216.0f        // 2^24
#define MASK_INV_SCALE (1.0f / 16777216.0f)
#define MASK_INV_SCALE_D (1.0 / 16777216.0)
#define COUNT_SHIFT 40
#define MASK40 0xFFFFFFFFFFULL        // low 40 bits
#define BIN21 0x1FFFFF

// k_out smem bit-table: 57344 words = 224 KB, 1 block/SM (proven config —
// smem hit-rate dominates occupancy for this gather).
#define SMEM_WORDS 57344
#define SMEM_BYTES (SMEM_WORDS * 4)

// Scratch (allocation-free rule: __device__ globals; zero-initialized at load)
__device__ unsigned long long g_hist[NBINS];   // 16 MB, packed count|mask
__device__ unsigned long long g_b64[NGRP];     // 32 MB: bins 0..2 of each group (21b each)
__device__ unsigned int       g_b32[NGRP];     // 16 MB: bin 3 of each group
__device__ unsigned int       g_flag[NFLAGW];  // 256 KB bit table
__device__ double             g_sumf_in, g_suml_in, g_avg;
__device__ unsigned long long g_mask_total;
__device__ unsigned int       g_bar1, g_bar2;  // software grid barriers

// ---------------------------------------------------------------------------
// K1: histogram accumulate + packed bin store (12B/4px). 4 pixels per thread
// (proven shape). Stream accesses evict-first. Thread 0 resets scalars;
// g_hist is left zeroed by the previous call's k_fused Phase B.
// ---------------------------------------------------------------------------
__global__ void __launch_bounds__(256) k_hist(const int* __restrict__ img,
                                              const float* __restrict__ mask) {
    int t = blockIdx.x * blockDim.x + threadIdx.x;   // 0 .. NPIX/4-1
    if (t == 0) {
        g_sumf_in = 0.0; g_suml_in = 0.0; g_avg = 0.0;
        g_mask_total = 0ULL;
        g_bar1 = 0u; g_bar2 = 0u;
    }
    if (t >= NPIX / 4) return;

    const int4* img4 = (const int4*)img;
    int4 a = __ldcs(&img4[t * 3 + 0]);
    int4 b = __ldcs(&img4[t * 3 + 1]);
    int4 c = __ldcs(&img4[t * 3 + 2]);
    float4 m = __ldcs(&((const float4*)mask)[t]);

    int bin0 = ((a.x >> 1) << 14) | ((a.y >> 1) << 7) | (a.z >> 1);
    int bin1 = ((a.w >> 1) << 14) | ((b.x >> 1) << 7) | (b.y >> 1);
    int bin2 = ((b.z >> 1) << 14) | ((b.w >> 1) << 7) | (c.x >> 1);
    int bin3 = ((c.y >> 1) << 14) | ((c.z >> 1) << 7) | (c.w >> 1);

    unsigned long long v0 = (1ULL << COUNT_SHIFT) | (unsigned long long)(m.x * MASK_SCALE + 0.5f);
    unsigned long long v1 = (1ULL << COUNT_SHIFT) | (unsigned long long)(m.y * MASK_SCALE + 0.5f);
    unsigned long long v2 = (1ULL << COUNT_SHIFT) | (unsigned long long)(m.z * MASK_SCALE + 0.5f);
    unsigned long long v3 = (1ULL << COUNT_SHIFT) | (unsigned long long)(m.w * MASK_SCALE + 0.5f);

    atomicAdd(&g_hist[bin0], v0);
    atomicAdd(&g_hist[bin1], v1);
    atomicAdd(&g_hist[bin2], v2);
    atomicAdd(&g_hist[bin3], v3);

    unsigned long long w = (unsigned long long)(unsigned int)bin0
                         | ((unsigned long long)(unsigned int)bin1 << 21)
                         | ((unsigned long long)(unsigned int)bin2 << 42);
    __stcs(&g_b64[t], w);
    __stcs(&g_b32[t], (unsigned int)bin3);
}

// ---------------------------------------------------------------------------
// K2 (fused): sums + log-ratio + flag table in one persistent kernel.
// (byte-identical to the proven R14/R15 version)
// ---------------------------------------------------------------------------
__device__ __forceinline__ void grid_barrier(unsigned int* bar) {
    __syncthreads();
    if (threadIdx.x == 0) {
        __threadfence();
        atomicAdd(bar, 1u);
        while (*((volatile unsigned int*)bar) < FGRID) { }
        __threadfence();
    }
    __syncthreads();
}

__global__ void __launch_bounds__(1024) k_fused(const float* __restrict__ full_in,
                                                const float* __restrict__ lines_in) {
    int tid  = threadIdx.x;
    int lane = tid & 31;
    int wid  = tid >> 5;
    int W    = blockIdx.x * 32 + wid;    // global warp id, 0..4735

    // ---------------- Phase A: sums ----------------
    unsigned long long msum = 0ULL;
    float fsum = 0.0f, lsum = 0.0f;
    #pragma unroll
    for (int j = 0; j < CPT; j++) {
        int c = W + j * FWARPS;
        if (c < NCHUNK) {                 // warp-uniform guard
            int bin = c * 32 + lane;
            unsigned long long h = g_hist[bin];
            msum += (h & MASK40);
            fsum += full_in[bin];
            lsum += lines_in[bin];
        }
    }
    for (int o = 16; o > 0; o >>= 1) {
        msum += __shfl_down_sync(0xFFFFFFFFu, msum, o);
        fsum += __shfl_down_sync(0xFFFFFFFFu, fsum, o);
        lsum += __shfl_down_sync(0xFFFFFFFFu, lsum, o);
    }
    __shared__ unsigned long long sm[32];
    __shared__ float sf[32], sl[32];
    if (lane == 0) { sm[wid] = msum; sf[wid] = fsum; sl[wid] = lsum; }
    __syncthreads();
    if (wid == 0) {
        msum = sm[lane]; fsum = sf[lane]; lsum = sl[lane];
        for (int o = 16; o > 0; o >>= 1) {
            msum += __shfl_down_sync(0xFFFFFFFFu, msum, o);
            fsum += __shfl_down_sync(0xFFFFFFFFu, fsum, o);
            lsum += __shfl_down_sync(0xFFFFFFFFu, lsum, o);
        }
        if (lane == 0) {
            atomicAdd(&g_mask_total, msum);
            atomicAdd(&g_sumf_in, (double)fsum);
            atomicAdd(&g_suml_in, (double)lsum);
        }
    }
    grid_barrier(&g_bar1);

    // Derive scalars (identical doubles in every block)
    __shared__ float sC, sInvSl;
    if (tid == 0) {
        double sfd = *((volatile double*)&g_sumf_in) + (double)NPIX + (double)NBINS;
        double sld = *((volatile double*)&g_suml_in)
                   + (double)(*((volatile unsigned long long*)&g_mask_total)) * MASK_INV_SCALE_D
                   + (double)NBINS * 1e-10;
        sC = (float)(log(sfd) - log(sld));
        sInvSl = (float)(1.0 / sld);
    }
    __syncthreads();
    float C = sC, inv_sl = sInvSl;

    // ---------------- Phase B: log ratios (register-resident) + avg ----------
    float lr[CPT];
    float avg = 0.0f;
    #pragma unroll
    for (int j = 0; j < CPT; j++) {
        int c = W + j * FWARPS;
        if (c < NCHUNK) {                 // L2-hot re-reads
            int bin = c * 32 + lane;
            unsigned long long h = g_hist[bin];
            g_hist[bin] = 0ULL;           // zero for next call (sole owner)
            float cnt = (float)(h >> COUNT_SHIFT);
            float ms  = (float)(h & MASK40) * MASK_INV_SCALE;
            float f = full_in[bin] + cnt + 1.0f;
            float l = lines_in[bin] + ms + 1e-10f;
            float v = __logf(l) - __logf(f) + C;   // no divide (proven bit-identical)
            lr[j] = v;
            avg += (l * inv_sl) * v;
        } else {
            lr[j] = 0.0f;
        }
    }
    for (int o = 16; o > 0; o >>= 1)
        avg += __shfl_down_sync(0xFFFFFFFFu, avg, o);
    __shared__ float sa[32];
    if (lane == 0) sa[wid] = avg;
    __syncthreads();
    if (wid == 0) {
        avg = sa[lane];
        for (int o = 16; o > 0; o >>= 1)
            avg += __shfl_down_sync(0xFFFFFFFFu, avg, o);
        if (lane == 0) atomicAdd(&g_avg, (double)avg);
    }
    grid_barrier(&g_bar2);

    // ---------------- Phase C: flag bits via ballot ----------------
    float avgf = (float)(*((volatile double*)&g_avg));
    #pragma unroll
    for (int j = 0; j < CPT; j++) {
        int c = W + j * FWARPS;
        if (c < NCHUNK) {                 // warp-uniform: full-warp ballot
            unsigned int m = __ballot_sync(0xFFFFFFFFu, lr[j] > avgf);
            if (lane == 0) g_flag[c] = m;
        }
    }
}

// ---------------------------------------------------------------------------
// K4: gather from packed bins (12B/4px). 224KB bit table in smem, rest via
// L2-resident g_flag. Streams evict-first. 148 blocks x 1024 threads.
// ---------------------------------------------------------------------------
__global__ void __launch_bounds__(1024) k_out(float* __restrict__ out) {
    extern __shared__ unsigned int s_flag[];
    for (int i = threadIdx.x; i < SMEM_WORDS; i += 1024)
        s_flag[i] = g_flag[i];
    __syncthreads();

    int stride = gridDim.x * 1024;
    for (int t = blockIdx.x * 1024 + threadIdx.x; t < NPIX / 4; t += stride) {
        unsigned long long ww = __ldcs(&g_b64[t]);
        unsigned int       xx = __ldcs(&g_b32[t]);
        int b0 = (int)( ww        & BIN21);
        int b1 = (int)((ww >> 21) & BIN21);
        int b2 = (int)( ww >> 42);
        int b3 = (int)xx;
        float4 o;
        {
            int w = b0 >> 5, bit = b0 & 31;
            unsigned int word = (w < SMEM_WORDS) ? s_flag[w] : __ldg(&g_flag[w]);
            o.x = (float)((word >> bit) & 1u);
        }
        {
            int w = b1 >> 5, bit = b1 & 31;
            unsigned int word = (w < SMEM_WORDS) ? s_flag[w] : __ldg(&g_flag[w]);
            o.y = (float)((word >> bit) & 1u);
        }
        {
            int w = b2 >> 5, bit = b2 & 31;
            unsigned int word = (w < SMEM_WORDS) ? s_flag[w] : __ldg(&g_flag[w]);
            o.z = (float)((word >> bit) & 1u);
        }
        {
            int w = b3 >> 5, bit = b3 & 31;
            unsigned int word = (w < SMEM_WORDS) ? s_flag[w] : __ldg(&g_flag[w]);
            o.w = (float)((word >> bit) & 1u);
        }
        __stcs(&((float4*)out)[t], o);
    }
}

extern "C" void kernel_launch(void* const* d_in, const int* in_sizes, int n_in,
                              void* d_out, int out_size) {
    const int*   img      = (const int*)d_in[0];
    const float* mask     = (const float*)d_in[1];
    const float* full_in  = (const float*)d_in[2];
    const float* lines_in = (const float*)d_in[3];
    float* out            = (float*)d_out;

    // Idempotent opt-in for 224KB dynamic smem (non-stream call; capture-safe).
    cudaFuncSetAttribute(k_out, cudaFuncAttributeMaxDynamicSharedMemorySize, SMEM_BYTES);

    k_hist <<<(NPIX / 4) / 256, 256>>>(img, mask);
    k_fused<<<FGRID, 1024>>>(full_in, lines_in);
    k_out  <<<148, 1024, SMEM_BYTES>>>(out);
}